// round 2
// baseline (speedup 1.0000x reference)
#include <cuda_runtime.h>

// Problem constants
#define NRED   100000      // reduction length
#define TT     32          // timesteps
#define KFEAT  512         // out features
#define THRESH 10.0f
#define KWTA   16

// GEMM tiling
#define SPLITS 73
#define KB     32
#define NTILES 43
#define CHUNK  (NTILES * KB)      // 1376
#define MTILE  256
#define WROWF  256                 // w_s row stride (floats), swizzled, no pad
#define RROW   68                  // r_s row stride (floats), padded
#define WBUF   (KB * WROWF)        // 8192
#define RBUF   (KB * RROW)         // 2176
#define SMEMB  ((2*WBUF + 2*RBUF) * 4)   // 82944 bytes

// Device scratch (static — no dynamic allocation allowed)
__device__ float g_rt2[(size_t)NRED * 64];        // transposed+duplicated rec_field, 25.6MB
__device__ float g_partial[SPLITS * KFEAT * TT];  // 4.8MB
__device__ float g_dot[KFEAT * TT];

typedef unsigned long long ull;

__device__ __forceinline__ void ffma2(ull& d, ull a, ull b) {
    asm("fma.rn.f32x2 %0, %1, %2, %0;" : "+l"(d) : "l"(a), "l"(b));
}
__device__ __forceinline__ float2 unpack2(ull v) {
    float2 f; asm("mov.b64 {%0, %1}, %2;" : "=f"(f.x), "=f"(f.y) : "l"(v)); return f;
}

// ---------------------------------------------------------------------------
// Transpose + duplicate: rt2[k][2t] = rt2[k][2t+1] = R[t][k]
// ---------------------------------------------------------------------------
__global__ void __launch_bounds__(256)
trans_kernel(const float* __restrict__ R) {
    __shared__ float s[32][129];
    const int k0 = blockIdx.x * 128;
    const int tid = threadIdx.x;
#pragma unroll
    for (int i = 0; i < 16; i++) {
        int idx = tid + 256 * i;
        int t = idx >> 7, k = idx & 127;
        s[t][k] = (k0 + k < NRED) ? R[(size_t)t * NRED + k0 + k] : 0.0f;
    }
    __syncthreads();
#pragma unroll
    for (int i = 0; i < 16; i++) {
        int idx = tid + 256 * i;
        int k = idx >> 5, t = idx & 31;
        if (k0 + k < NRED) {
            float v = s[t][k];
            ((float2*)g_rt2)[(size_t)(k0 + k) * 32 + t] = make_float2(v, v);
        }
    }
}

// ---------------------------------------------------------------------------
// GEMM: partial[split][feat][t] over k-chunk. grid (73,2) x 512 threads.
// w_s: [k][m] with XOR-swizzled 4-float units; r_s: [k][t-dup-pairs].
// ---------------------------------------------------------------------------
__global__ void __launch_bounds__(512, 1)
gemm_kernel(const float* __restrict__ W) {
    extern __shared__ float smem[];
    float* w_s = smem;                 // [2][KB][256]
    float* r_s = smem + 2 * WBUF;      // [2][KB][RROW]

    const int tid   = threadIdx.x;
    const int split = blockIdx.x;
    const int m0    = blockIdx.y * MTILE;
    const int kbase = split * CHUNK;

    // W loader: lanes run along k (coalesced, nL=4), 4 m-rows per warp
    const int lane = tid & 31, wrp = tid >> 5;
    const int kq = lane & 7;                  // k-quad 0..7
    const int mb = (lane >> 3) + 4 * wrp;     // m base 0..63 (+64*i)
    // R loader
    const int rk = tid >> 4;                  // k row 0..31
    const int rq = tid & 15;                  // 16B quad 0..15
    // Compute mapping: 8 feats x 2 timesteps per thread
    const int fg = tid >> 4;                  // feat group 0..31
    const int tp = tid & 15;                  // t-pair 0..15
    const int f0 = fg * 8, f4 = fg * 8 + 4;

    ull acc[4][2];
#pragma unroll
    for (int p = 0; p < 4; p++) { acc[p][0] = 0ull; acc[p][1] = 0ull; }

    float4 wreg0, wreg1, wreg2, wreg3, rreg;
    const float4 z4 = make_float4(0.f, 0.f, 0.f, 0.f);
    const float* Rt = g_rt2;

#define LOAD_TILE(TL) do {                                                   \
    int kb_ = kbase + (TL) * KB;                                             \
    int kp_ = kb_ + kq * 4;                                                  \
    const float* wp_ = W + (size_t)(m0 + mb) * NRED + kp_;                   \
    bool ok_ = (kp_ < NRED);                                                 \
    wreg0 = ok_ ? *(const float4*)(wp_) : z4;                                \
    wreg1 = ok_ ? *(const float4*)(wp_ + (size_t)64 * NRED) : z4;            \
    wreg2 = ok_ ? *(const float4*)(wp_ + (size_t)128 * NRED) : z4;           \
    wreg3 = ok_ ? *(const float4*)(wp_ + (size_t)192 * NRED) : z4;           \
    int kr_ = kb_ + rk;                                                      \
    rreg = (kr_ < NRED) ? *(const float4*)(Rt + (size_t)kr_ * 64 + rq * 4)   \
                        : z4;                                                \
} while (0)

#define STS_ONE(wb_, mx_, V) do {                                            \
    (wb_)[(kq * 4 + 0) * WROWF + (mx_)] = (V).x;                             \
    (wb_)[(kq * 4 + 1) * WROWF + (mx_)] = (V).y;                             \
    (wb_)[(kq * 4 + 2) * WROWF + (mx_)] = (V).z;                             \
    (wb_)[(kq * 4 + 3) * WROWF + (mx_)] = (V).w;                             \
} while (0)

#define STS_TILE(BUF) do {                                                   \
    float* wb_ = w_s + (BUF) * WBUF;                                         \
    int mx_ = mb ^ (kq * 4);                                                 \
    STS_ONE(wb_, mx_,       wreg0);                                          \
    STS_ONE(wb_, mx_ + 64,  wreg1);                                          \
    STS_ONE(wb_, mx_ + 128, wreg2);                                          \
    STS_ONE(wb_, mx_ + 192, wreg3);                                          \
    *(float4*)(r_s + (BUF) * RBUF + rk * RROW + rq * 4) = rreg;              \
} while (0)

#define COMPUTE(BUF) do {                                                    \
    const float* wb_ = w_s + (BUF) * WBUF;                                   \
    const float* rb_ = r_s + (BUF) * RBUF + tp * 4;                          \
    _Pragma("unroll")                                                        \
    for (int kk_ = 0; kk_ < KB; kk_++) {                                     \
        int s_ = ((kk_ >> 2) & 7) * 4;                                       \
        ulonglong2 a01 = *(const ulonglong2*)(wb_ + kk_ * WROWF + (f0 ^ s_));\
        ulonglong2 a23 = *(const ulonglong2*)(wb_ + kk_ * WROWF + (f4 ^ s_));\
        ulonglong2 bb  = *(const ulonglong2*)(rb_ + kk_ * RROW);             \
        ffma2(acc[0][0], a01.x, bb.x); ffma2(acc[0][1], a01.x, bb.y);        \
        ffma2(acc[1][0], a01.y, bb.x); ffma2(acc[1][1], a01.y, bb.y);        \
        ffma2(acc[2][0], a23.x, bb.x); ffma2(acc[2][1], a23.x, bb.y);        \
        ffma2(acc[3][0], a23.y, bb.x); ffma2(acc[3][1], a23.y, bb.y);        \
    }                                                                        \
} while (0)

    LOAD_TILE(0);
    STS_TILE(0);
    __syncthreads();

    for (int tl = 0; tl < NTILES; tl++) {
        if (tl + 1 < NTILES) LOAD_TILE(tl + 1);
        COMPUTE(tl & 1);
        if (tl + 1 < NTILES) {
            STS_TILE((tl + 1) & 1);
            __syncthreads();
        }
    }

    // Epilogue: acc[p][j] = (feat 2p @ t(2tp+j), feat 2p+1 @ t(2tp+j))
    const size_t gbase = ((size_t)split * KFEAT + m0 + fg * 8) * TT;
#pragma unroll
    for (int p = 0; p < 4; p++) {
        float2 u0 = unpack2(acc[p][0]);
        float2 u1 = unpack2(acc[p][1]);
        *(float2*)(g_partial + gbase + (2 * p) * TT + 2 * tp)     = make_float2(u0.x, u1.x);
        *(float2*)(g_partial + gbase + (2 * p + 1) * TT + 2 * tp) = make_float2(u0.y, u1.y);
    }
}

// ---------------------------------------------------------------------------
// Reduce partials across splits
// ---------------------------------------------------------------------------
__global__ void __launch_bounds__(256)
reduce_kernel() {
    const int j = blockIdx.x * 256 + threadIdx.x;
    float s = 0.0f;
#pragma unroll 8
    for (int sp = 0; sp < SPLITS; sp++) s += g_partial[sp * (KFEAT * TT) + j];
    g_dot[j] = s;
}

// ---------------------------------------------------------------------------
// Winner selection (exact reference math), 1 block x 512 threads
// ---------------------------------------------------------------------------
__global__ void __launch_bounds__(512, 1)
winner_kernel(float* __restrict__ out) {
    __shared__ float tot_s[KFEAT];
    __shared__ float red_s[16];
    __shared__ float v_s;

    const int k = threadIdx.x;

    float pot[TT];
    int nspk = 0;
#pragma unroll
    for (int t = 0; t < TT; t++) {
        float d = g_dot[k * TT + t];
        float p = (d > THRESH) ? d : 0.0f;
        pot[t] = p;
        nspk += (p > 0.0f) ? 1 : 0;
    }
    int first = TT - nspk;
    if (first > TT - 1) first = TT - 1;
    if (first < 0) first = 0;
    float dv = g_dot[k * TT + first];
    float value = (dv > THRESH) ? dv : 0.0f;
    float sval = (nspk > 0) ? value : 0.0f;

    float m = sval;
#pragma unroll
    for (int o = 16; o > 0; o >>= 1)
        m = fmaxf(m, __shfl_xor_sync(0xffffffffu, m, o));
    if ((k & 31) == 0) red_s[k >> 5] = m;
    __syncthreads();
    if (k == 0) {
        float mm = red_s[0];
#pragma unroll
        for (int i = 1; i < 16; i++) mm = fmaxf(mm, red_s[i]);
        v_s = mm * (float)TT;
    }
    __syncthreads();
    const float v = v_s;

    const float fns = (float)nspk;
    const float total = fns * value + fns * v;
    tot_s[k] = total;
    __syncthreads();

    // Rank-count == sequential suppressive argmax with first-index tie-break
    int cnt = 0;
    const float4* t4 = (const float4*)tot_s;
#pragma unroll 8
    for (int jj = 0; jj < KFEAT / 4; jj++) {
        float4 tv = t4[jj];
        const int j0 = jj * 4;
        cnt += ((tv.x > total) || (tv.x == total && (j0 + 0) < k)) ? 1 : 0;
        cnt += ((tv.y > total) || (tv.y == total && (j0 + 1) < k)) ? 1 : 0;
        cnt += ((tv.z > total) || (tv.z == total && (j0 + 2) < k)) ? 1 : 0;
        cnt += ((tv.w > total) || (tv.w == total && (j0 + 3) < k)) ? 1 : 0;
    }
    const bool win = (total > 0.0f) && (cnt < KWTA);

#pragma unroll
    for (int t = 0; t < TT; t++)
        out[t * KFEAT + k] = (win && pot[t] > 0.0f) ? 1.0f : 0.0f;
}

// ---------------------------------------------------------------------------
extern "C" void kernel_launch(void* const* d_in, const int* in_sizes, int n_in,
                              void* d_out, int out_size) {
    const float* a = (const float*)d_in[0];
    const float* b = (const float*)d_in[1];
    const float* rec = a;
    const float* wgt = b;
    if (in_sizes[0] > in_sizes[1]) { rec = b; wgt = a; }

    cudaFuncSetAttribute(gemm_kernel,
                         cudaFuncAttributeMaxDynamicSharedMemorySize, SMEMB);

    trans_kernel<<<(NRED + 127) / 128, 256>>>(rec);
    dim3 grid(SPLITS, 2);
    gemm_kernel<<<grid, 512, SMEMB>>>(wgt);
    reduce_kernel<<<(KFEAT * TT) / 256, 256>>>();
    winner_kernel<<<1, 512>>>((float*)d_out);
}

// round 4
// speedup vs baseline: 1.9941x; 1.9941x over previous
#include <cuda_runtime.h>
#include <cuda_bf16.h>
#include <cstdint>

// ---------------------------------------------------------------------------
// Problem constants
#define NRED   100000
#define TT     32
#define KFEAT  512
#define THRESH 10.0f
#define KWTA   16

// GEMM tiling: 37 k-splits x 4 m-tiles = 148 CTAs (one wave)
#define SPLITS 37
#define KTILE  64
#define NT     43
#define CHUNK  (KTILE * NT)        // 2752
#define KPAD   (SPLITS * CHUNK)    // 101824
#define MTILE  128

// smem layout (dynamic): A: 2 buffers x [256 rows][128B] bf16 (hi rows 0-127,
// lo rows 128-255). B: 2 buffers x [64 rows][128B] bf16 (hi t 0-31, lo 32-63).
#define SM_A    0
#define SM_ASTG 32768
#define SM_B    (2 * SM_ASTG)      // 65536
#define SM_BSTG 8192
#define SMEMB   (SM_B + 2 * SM_BSTG)   // 81920

// Device scratch (static — no dynamic allocation allowed)
__device__ __nv_bfloat16 g_B[(size_t)64 * KPAD];   // split rec_field, 13MB
__device__ float g_partial[SPLITS * TT * KFEAT];   // [split][t][feat]
__device__ float g_dot[TT * KFEAT];                // [t][feat]

// ---------------------------------------------------------------------------
__device__ __forceinline__ uint32_t smem_u32(const void* p) {
    uint32_t a;
    asm("{ .reg .u64 t; cvta.to.shared.u64 t, %1; cvt.u32.u64 %0, t; }"
        : "=r"(a) : "l"(p));
    return a;
}
__device__ __forceinline__ uint32_t sw128(uint32_t off) {
    return off ^ ((off >> 3) & 0x70);
}
__device__ __forceinline__ uint32_t packbf(__nv_bfloat16 a, __nv_bfloat16 b) {
    __nv_bfloat162 v; v.x = a; v.y = b;
    return *reinterpret_cast<uint32_t*>(&v);
}
__device__ __forceinline__ void split2(float x, __nv_bfloat16& h, __nv_bfloat16& l) {
    h = __float2bfloat16(x);
    l = __float2bfloat16(x - __bfloat162float(h));
}
#define LDSM4(R, ADDR)                                                        \
    asm volatile("ldmatrix.sync.aligned.m8n8.x4.shared.b16 {%0,%1,%2,%3}, [%4];" \
                 : "=r"((R)[0]), "=r"((R)[1]), "=r"((R)[2]), "=r"((R)[3])     \
                 : "r"(ADDR))
#define MMA16816(D, A, B0, B1)                                                \
    asm volatile("mma.sync.aligned.m16n8k16.row.col.f32.bf16.bf16.f32 "       \
                 "{%0,%1,%2,%3}, {%4,%5,%6,%7}, {%8,%9}, {%0,%1,%2,%3};"      \
                 : "+f"((D)[0]), "+f"((D)[1]), "+f"((D)[2]), "+f"((D)[3])     \
                 : "r"((A)[0]), "r"((A)[1]), "r"((A)[2]), "r"((A)[3]),        \
                   "r"(B0), "r"(B1))

// ---------------------------------------------------------------------------
// Split rec_field into bf16 hi/lo: g_B[t][k]=hi, g_B[t+32][k]=lo (k zero-padded)
// ---------------------------------------------------------------------------
__global__ void __launch_bounds__(256)
conv_kernel(const float* __restrict__ R) {
    const int k = blockIdx.x * 256 + threadIdx.x;
    if (k >= KPAD) return;
#pragma unroll 4
    for (int t = 0; t < TT; t++) {
        float x = (k < NRED) ? R[(size_t)t * NRED + k] : 0.0f;
        __nv_bfloat16 h, l;
        split2(x, h, l);
        g_B[(size_t)t * KPAD + k] = h;
        g_B[(size_t)(t + 32) * KPAD + k] = l;
    }
}

// ---------------------------------------------------------------------------
// GEMM via mma.sync bf16 split. grid (37,4), 256 threads (8 warps).
// Each warp: 16 m-rows x 64 n-cols; D folds cols t / t+32 in epilogue.
// ---------------------------------------------------------------------------
__global__ void __launch_bounds__(256, 1)
gemm_kernel(const float* __restrict__ W) {
    extern __shared__ char smem[];
    const uint32_t sb = smem_u32(smem);

    const int tid  = threadIdx.x;
    const int lane = tid & 31;
    const int wrp  = tid >> 5;
    const int split = blockIdx.x;
    const int m0    = blockIdx.y * MTILE;
    const int kbase = split * CHUNK;

    // ---- loader indices ----
    const int row_off = lane >> 4;            // 0..1
    const int kq      = lane & 15;            // k-quad 0..15
    const int brow    = tid >> 2;             // 0..63
    const int bq      = tid & 3;              // 0..3

    // ---- ldmatrix indices ----
    const int arow = wrp * 16 + (lane & 7) + ((lane >> 3) & 1) * 8;
    const uint32_t a_rb  = (uint32_t)arow * 128;
    const uint32_t a_xr  = (uint32_t)(arow & 7) << 4;
    const uint32_t a_kb0 = ((lane >> 4) & 1) * 16;
    const int browl = (lane & 7) + ((lane >> 4) & 1) * 8;
    const uint32_t b_rb  = (uint32_t)browl * 128;
    const uint32_t b_xr  = (uint32_t)(lane & 7) << 4;
    const uint32_t b_kb0 = ((lane >> 3) & 1) * 16;

    float d[8][4];
#pragma unroll
    for (int i = 0; i < 8; i++)
#pragma unroll
        for (int j = 0; j < 4; j++) d[i][j] = 0.0f;

    float4 wr[8];
    uint4 bv0, bv1;
    const float4 z4 = make_float4(0.f, 0.f, 0.f, 0.f);

#define LOAD_TILE(TL) do {                                                   \
    const int kp_ = kbase + (TL) * KTILE + kq * 4;                           \
    const bool ok_ = (kp_ < NRED);                                           \
    const float* wp_ = W + (size_t)(m0 + wrp * 2 + row_off) * NRED + kp_;    \
    _Pragma("unroll")                                                        \
    for (int i = 0; i < 8; i++)                                              \
        wr[i] = ok_ ? *(const float4*)(wp_ + (size_t)16 * i * NRED) : z4;    \
    const __nv_bfloat16* bgp_ = g_B + (size_t)brow * KPAD                    \
                              + (size_t)(kbase + (TL) * KTILE) + bq * 16;    \
    bv0 = *(const uint4*)(bgp_);                                             \
    bv1 = *(const uint4*)(bgp_ + 8);                                         \
} while (0)

#define STS_TILE(BUF) do {                                                   \
    char* ab_ = smem + SM_A + (BUF) * SM_ASTG;                               \
    _Pragma("unroll")                                                        \
    for (int i = 0; i < 8; i++) {                                            \
        const int row_ = i * 16 + wrp * 2 + row_off;                         \
        const uint32_t sw_ = sw128((uint32_t)row_ * 128 + kq * 8);           \
        float4 f_ = wr[i];                                                   \
        __nv_bfloat16 h0,h1,h2,h3,l0,l1,l2,l3;                               \
        split2(f_.x, h0, l0); split2(f_.y, h1, l1);                          \
        split2(f_.z, h2, l2); split2(f_.w, h3, l3);                          \
        *(uint2*)(ab_ + sw_)         = make_uint2(packbf(h0,h1), packbf(h2,h3)); \
        *(uint2*)(ab_ + sw_ + 16384) = make_uint2(packbf(l0,l1), packbf(l2,l3)); \
    }                                                                        \
    char* bb_ = smem + SM_B + (BUF) * SM_BSTG;                               \
    const uint32_t boff_ = (uint32_t)brow * 128 + bq * 32;                   \
    *(uint4*)(bb_ + sw128(boff_))      = bv0;                                \
    *(uint4*)(bb_ + sw128(boff_ + 16)) = bv1;                                \
} while (0)

#define COMPUTE(BUF) do {                                                    \
    const uint32_t sa_ = sb + SM_A + (BUF) * SM_ASTG;                        \
    const uint32_t sB_ = sb + SM_B + (BUF) * SM_BSTG;                        \
    _Pragma("unroll")                                                        \
    for (int ks = 0; ks < 4; ks++) {                                         \
        uint32_t ah[4], al[4], bf[4][4];                                     \
        const uint32_t akb_ = ((uint32_t)(ks * 32) + a_kb0) ^ a_xr;          \
        LDSM4(ah, sa_ + a_rb + akb_);                                        \
        LDSM4(al, sa_ + 16384 + a_rb + akb_);                                \
        const uint32_t bkb_ = ((uint32_t)(ks * 32) + b_kb0) ^ b_xr;          \
        _Pragma("unroll")                                                    \
        for (int p = 0; p < 4; p++)                                          \
            LDSM4(bf[p], sB_ + (uint32_t)p * 2048 + b_rb + bkb_);            \
        _Pragma("unroll")                                                    \
        for (int p = 0; p < 4; p++) {                                        \
            MMA16816(d[2*p],   ah, bf[p][0], bf[p][1]);                      \
            MMA16816(d[2*p],   al, bf[p][0], bf[p][1]);                      \
            MMA16816(d[2*p+1], ah, bf[p][2], bf[p][3]);                      \
            MMA16816(d[2*p+1], al, bf[p][2], bf[p][3]);                      \
        }                                                                    \
    }                                                                        \
} while (0)

    LOAD_TILE(0);
    STS_TILE(0);
    __syncthreads();

    for (int tl = 0; tl < NT; tl++) {
        if (tl + 1 < NT) LOAD_TILE(tl + 1);
        COMPUTE(tl & 1);
        if (tl + 1 < NT) {
            STS_TILE((tl + 1) & 1);
            __syncthreads();
        }
    }

    // ---- epilogue: fold cols t and t+32, write [split][t][feat] ----
    const int rr = wrp * 16 + (lane >> 2);
    const int c0 = (lane & 3) * 2;
    float* gp = g_partial + (size_t)split * (TT * KFEAT) + m0;
#pragma unroll
    for (int nt = 0; nt < 4; nt++) {
        const int t0 = nt * 8 + c0;
        gp[(size_t)t0 * KFEAT + rr]           = d[nt][0] + d[nt + 4][0];
        gp[(size_t)(t0 + 1) * KFEAT + rr]     = d[nt][1] + d[nt + 4][1];
        gp[(size_t)t0 * KFEAT + rr + 8]       = d[nt][2] + d[nt + 4][2];
        gp[(size_t)(t0 + 1) * KFEAT + rr + 8] = d[nt][3] + d[nt + 4][3];
    }
}

// ---------------------------------------------------------------------------
// Reduce partials across splits: g_dot[t][feat]
// ---------------------------------------------------------------------------
__global__ void __launch_bounds__(256)
reduce_kernel() {
    const int j = blockIdx.x * 256 + threadIdx.x;
    float s = 0.0f;
#pragma unroll 8
    for (int sp = 0; sp < SPLITS; sp++) s += g_partial[sp * (TT * KFEAT) + j];
    g_dot[j] = s;
}

// ---------------------------------------------------------------------------
// Winner selection (exact reference math), 1 block x 512 threads, coalesced.
// ---------------------------------------------------------------------------
__global__ void __launch_bounds__(512, 1)
winner_kernel(float* __restrict__ out) {
    __shared__ float tot_s[KFEAT];
    __shared__ float red_s[16];
    __shared__ float v_s;

    const int k = threadIdx.x;

    float pot[TT];
    int nspk = 0;
#pragma unroll
    for (int t = 0; t < TT; t++) {
        float dd = g_dot[t * KFEAT + k];
        float p = (dd > THRESH) ? dd : 0.0f;
        pot[t] = p;
        nspk += (p > 0.0f) ? 1 : 0;
    }
    int first = TT - nspk;
    if (first > TT - 1) first = TT - 1;
    if (first < 0) first = 0;
    float dv = g_dot[first * KFEAT + k];
    float value = (dv > THRESH) ? dv : 0.0f;
    float sval = (nspk > 0) ? value : 0.0f;

    float m = sval;
#pragma unroll
    for (int o = 16; o > 0; o >>= 1)
        m = fmaxf(m, __shfl_xor_sync(0xffffffffu, m, o));
    if ((k & 31) == 0) red_s[k >> 5] = m;
    __syncthreads();
    if (k == 0) {
        float mm = red_s[0];
#pragma unroll
        for (int i = 1; i < 16; i++) mm = fmaxf(mm, red_s[i]);
        v_s = mm * (float)TT;
    }
    __syncthreads();
    const float v = v_s;

    const float fns = (float)nspk;
    const float total = fns * value + fns * v;
    tot_s[k] = total;
    __syncthreads();

    // Rank-count == sequential suppressive argmax with first-index tie-break
    int cnt = 0;
    const float4* t4 = (const float4*)tot_s;
#pragma unroll 8
    for (int jj = 0; jj < KFEAT / 4; jj++) {
        float4 tv = t4[jj];
        const int j0 = jj * 4;
        cnt += ((tv.x > total) || (tv.x == total && (j0 + 0) < k)) ? 1 : 0;
        cnt += ((tv.y > total) || (tv.y == total && (j0 + 1) < k)) ? 1 : 0;
        cnt += ((tv.z > total) || (tv.z == total && (j0 + 2) < k)) ? 1 : 0;
        cnt += ((tv.w > total) || (tv.w == total && (j0 + 3) < k)) ? 1 : 0;
    }
    const bool win = (total > 0.0f) && (cnt < KWTA);

#pragma unroll
    for (int t = 0; t < TT; t++)
        out[t * KFEAT + k] = (win && pot[t] > 0.0f) ? 1.0f : 0.0f;
}

// ---------------------------------------------------------------------------
extern "C" void kernel_launch(void* const* d_in, const int* in_sizes, int n_in,
                              void* d_out, int out_size) {
    const float* a = (const float*)d_in[0];
    const float* b = (const float*)d_in[1];
    const float* rec = a;
    const float* wgt = b;
    if (in_sizes[0] > in_sizes[1]) { rec = b; wgt = a; }

    cudaFuncSetAttribute(gemm_kernel,
                         cudaFuncAttributeMaxDynamicSharedMemorySize, SMEMB);

    conv_kernel<<<(KPAD + 255) / 256, 256>>>(rec);
    dim3 grid(SPLITS, 4);
    gemm_kernel<<<grid, 256, SMEMB>>>(wgt);
    reduce_kernel<<<(TT * KFEAT) / 256, 256>>>();
    winner_kernel<<<1, 512>>>((float*)d_out);
}

// round 5
// speedup vs baseline: 1.9948x; 1.0004x over previous
#include <cuda_runtime.h>
#include <cuda_bf16.h>
#include <cstdint>

// ---------------------------------------------------------------------------
// Problem constants
#define NRED   100000
#define TT     32
#define KFEAT  512
#define THRESH 10.0f
#define KWTA   16

// GEMM tiling: 37 k-splits x 4 m-tiles = 148 CTAs (one wave)
#define SPLITS 37
#define KTILE  64
#define NT     43
#define CHUNK  (KTILE * NT)        // 2752
#define KPAD   (SPLITS * CHUNK)    // 101824
#define MTILE  128

// smem layout: A: 2 buffers x [256 rows][128B] bf16 (hi rows 0-127, lo 128-255)
// B: 2 buffers x [64 rows][128B] bf16 (hi t 0-31, lo t 32-63)
#define SM_A    0
#define SM_ASTG 32768
#define SM_B    (2 * SM_ASTG)      // 65536
#define SM_BSTG 8192
#define SMEMB   (SM_B + 2 * SM_BSTG)   // 81920

// Device scratch (static — no dynamic allocation allowed)
__device__ __nv_bfloat16 g_B[(size_t)64 * KPAD];   // split rec_field, 13MB
__device__ float g_partial[SPLITS * TT * KFEAT];   // [split][t][feat]
__device__ float g_dot[TT * KFEAT];                // [t][feat]

// ---------------------------------------------------------------------------
__device__ __forceinline__ uint32_t smem_u32(const void* p) {
    uint32_t a;
    asm("{ .reg .u64 t; cvta.to.shared.u64 t, %1; cvt.u32.u64 %0, t; }"
        : "=r"(a) : "l"(p));
    return a;
}
__device__ __forceinline__ uint32_t sw128(uint32_t off) {
    return off ^ ((off >> 3) & 0x70);
}
__device__ __forceinline__ uint32_t packbf(__nv_bfloat16 a, __nv_bfloat16 b) {
    __nv_bfloat162 v; v.x = a; v.y = b;
    return *reinterpret_cast<uint32_t*>(&v);
}
__device__ __forceinline__ void split2(float x, __nv_bfloat16& h, __nv_bfloat16& l) {
    h = __float2bfloat16(x);
    l = __float2bfloat16(x - __bfloat162float(h));
}
#define LDSM4(R, ADDR)                                                        \
    asm volatile("ldmatrix.sync.aligned.m8n8.x4.shared.b16 {%0,%1,%2,%3}, [%4];" \
                 : "=r"((R)[0]), "=r"((R)[1]), "=r"((R)[2]), "=r"((R)[3])     \
                 : "r"(ADDR))
#define MMA16816(D, A, B0, B1)                                                \
    asm volatile("mma.sync.aligned.m16n8k16.row.col.f32.bf16.bf16.f32 "       \
                 "{%0,%1,%2,%3}, {%4,%5,%6,%7}, {%8,%9}, {%0,%1,%2,%3};"      \
                 : "+f"((D)[0]), "+f"((D)[1]), "+f"((D)[2]), "+f"((D)[3])     \
                 : "r"((A)[0]), "r"((A)[1]), "r"((A)[2]), "r"((A)[3]),        \
                   "r"(B0), "r"(B1))

// ---------------------------------------------------------------------------
// Split rec_field into bf16 hi/lo (vectorized, 4 k per thread).
// NRED and KPAD are multiples of 4.
// ---------------------------------------------------------------------------
__global__ void __launch_bounds__(256)
conv_kernel(const float* __restrict__ R) {
    const int k4 = (blockIdx.x * 256 + threadIdx.x) * 4;
    if (k4 >= KPAD) return;
    const bool ok = (k4 < NRED);
#pragma unroll 4
    for (int t = 0; t < TT; t++) {
        float4 x = ok ? *(const float4*)(R + (size_t)t * NRED + k4)
                      : make_float4(0.f, 0.f, 0.f, 0.f);
        __nv_bfloat16 h0,h1,h2,h3,l0,l1,l2,l3;
        split2(x.x, h0, l0); split2(x.y, h1, l1);
        split2(x.z, h2, l2); split2(x.w, h3, l3);
        *(uint2*)(g_B + (size_t)t * KPAD + k4)        = make_uint2(packbf(h0,h1), packbf(h2,h3));
        *(uint2*)(g_B + (size_t)(t + 32) * KPAD + k4) = make_uint2(packbf(l0,l1), packbf(l2,l3));
    }
}

// ---------------------------------------------------------------------------
// GEMM via mma.sync bf16 3-term split (hi*hi, hi*lo, lo*hi; lo*lo dropped).
// grid (37,4), 256 threads (8 warps). Warp: 16 m-rows x 64 n-cols.
// ---------------------------------------------------------------------------
__global__ void __launch_bounds__(256, 1)
gemm_kernel(const float* __restrict__ W) {
    extern __shared__ char smem[];
    const uint32_t sb = smem_u32(smem);

    const int tid  = threadIdx.x;
    const int lane = tid & 31;
    const int wrp  = tid >> 5;
    const int split = blockIdx.x;
    const int m0    = blockIdx.y * MTILE;
    const int kbase = split * CHUNK;

    // loader indices
    const int row_off = lane >> 4;
    const int kq      = lane & 15;
    const int brow    = tid >> 2;
    const int bq      = tid & 3;

    // ldmatrix indices
    const int arow = wrp * 16 + (lane & 7) + ((lane >> 3) & 1) * 8;
    const uint32_t a_rb  = (uint32_t)arow * 128;
    const uint32_t a_xr  = (uint32_t)(arow & 7) << 4;
    const uint32_t a_kb0 = ((lane >> 4) & 1) * 16;
    const int browl = (lane & 7) + ((lane >> 4) & 1) * 8;
    const uint32_t b_rb  = (uint32_t)browl * 128;
    const uint32_t b_xr  = (uint32_t)(lane & 7) << 4;
    const uint32_t b_kb0 = ((lane >> 3) & 1) * 16;

    float d[8][4];
#pragma unroll
    for (int i = 0; i < 8; i++)
#pragma unroll
        for (int j = 0; j < 4; j++) d[i][j] = 0.0f;

    float4 wr[8];
    uint4 bv0, bv1;
    const float4 z4 = make_float4(0.f, 0.f, 0.f, 0.f);

#define LOAD_TILE(TL) do {                                                   \
    const int kp_ = kbase + (TL) * KTILE + kq * 4;                           \
    const bool ok_ = (kp_ < NRED);                                           \
    const float* wp_ = W + (size_t)(m0 + wrp * 2 + row_off) * NRED + kp_;    \
    _Pragma("unroll")                                                        \
    for (int i = 0; i < 8; i++)                                              \
        wr[i] = ok_ ? *(const float4*)(wp_ + (size_t)16 * i * NRED) : z4;    \
    const __nv_bfloat16* bgp_ = g_B + (size_t)brow * KPAD                    \
                              + (size_t)(kbase + (TL) * KTILE) + bq * 16;    \
    bv0 = *(const uint4*)(bgp_);                                             \
    bv1 = *(const uint4*)(bgp_ + 8);                                         \
} while (0)

#define STS_TILE(BUF) do {                                                   \
    char* ab_ = smem + SM_A + (BUF) * SM_ASTG;                               \
    _Pragma("unroll")                                                        \
    for (int i = 0; i < 8; i++) {                                            \
        const int row_ = i * 16 + wrp * 2 + row_off;                         \
        const uint32_t sw_ = sw128((uint32_t)row_ * 128 + kq * 8);           \
        float4 f_ = wr[i];                                                   \
        __nv_bfloat16 h0,h1,h2,h3,l0,l1,l2,l3;                               \
        split2(f_.x, h0, l0); split2(f_.y, h1, l1);                          \
        split2(f_.z, h2, l2); split2(f_.w, h3, l3);                          \
        *(uint2*)(ab_ + sw_)         = make_uint2(packbf(h0,h1), packbf(h2,h3)); \
        *(uint2*)(ab_ + sw_ + 16384) = make_uint2(packbf(l0,l1), packbf(l2,l3)); \
    }                                                                        \
    char* bb_ = smem + SM_B + (BUF) * SM_BSTG;                               \
    const uint32_t boff_ = (uint32_t)brow * 128 + bq * 32;                   \
    *(uint4*)(bb_ + sw128(boff_))      = bv0;                                \
    *(uint4*)(bb_ + sw128(boff_ + 16)) = bv1;                                \
} while (0)

// A-hi x full stacked B (p=0..3); A-lo x B-hi only (p=0,1). lo*lo dropped.
#define COMPUTE(BUF) do {                                                    \
    const uint32_t sa_ = sb + SM_A + (BUF) * SM_ASTG;                        \
    const uint32_t sB_ = sb + SM_B + (BUF) * SM_BSTG;                        \
    _Pragma("unroll")                                                        \
    for (int ks = 0; ks < 4; ks++) {                                         \
        uint32_t ah[4], al[4], bf[4][4];                                     \
        const uint32_t akb_ = ((uint32_t)(ks * 32) + a_kb0) ^ a_xr;          \
        LDSM4(ah, sa_ + a_rb + akb_);                                        \
        LDSM4(al, sa_ + 16384 + a_rb + akb_);                                \
        const uint32_t bkb_ = ((uint32_t)(ks * 32) + b_kb0) ^ b_xr;          \
        _Pragma("unroll")                                                    \
        for (int p = 0; p < 4; p++)                                          \
            LDSM4(bf[p], sB_ + (uint32_t)p * 2048 + b_rb + bkb_);            \
        _Pragma("unroll")                                                    \
        for (int p = 0; p < 4; p++) {                                        \
            MMA16816(d[2*p],   ah, bf[p][0], bf[p][1]);                      \
            MMA16816(d[2*p+1], ah, bf[p][2], bf[p][3]);                      \
            if (p < 2) {                                                     \
                MMA16816(d[2*p],   al, bf[p][0], bf[p][1]);                  \
                MMA16816(d[2*p+1], al, bf[p][2], bf[p][3]);                  \
            }                                                                \
        }                                                                    \
    }                                                                        \
} while (0)

    LOAD_TILE(0);
    STS_TILE(0);
    __syncthreads();

    for (int tl = 0; tl < NT; tl++) {
        if (tl + 1 < NT) LOAD_TILE(tl + 1);
        COMPUTE(tl & 1);
        if (tl + 1 < NT) {
            STS_TILE((tl + 1) & 1);
            __syncthreads();
        }
    }

    // epilogue: fold cols t and t+32, write [split][t][feat]
    const int rr = wrp * 16 + (lane >> 2);
    const int c0 = (lane & 3) * 2;
    float* gp = g_partial + (size_t)split * (TT * KFEAT) + m0;
#pragma unroll
    for (int nt = 0; nt < 4; nt++) {
        const int t0 = nt * 8 + c0;
        gp[(size_t)t0 * KFEAT + rr]           = d[nt][0] + d[nt + 4][0];
        gp[(size_t)(t0 + 1) * KFEAT + rr]     = d[nt][1] + d[nt + 4][1];
        gp[(size_t)t0 * KFEAT + rr + 8]       = d[nt][2] + d[nt + 4][2];
        gp[(size_t)(t0 + 1) * KFEAT + rr + 8] = d[nt][3] + d[nt + 4][3];
    }
}

// ---------------------------------------------------------------------------
// Reduce partials across splits: g_dot[t][feat]
// ---------------------------------------------------------------------------
__global__ void __launch_bounds__(256)
reduce_kernel() {
    const int j = blockIdx.x * 256 + threadIdx.x;
    float s = 0.0f;
#pragma unroll 8
    for (int sp = 0; sp < SPLITS; sp++) s += g_partial[sp * (TT * KFEAT) + j];
    g_dot[j] = s;
}

// ---------------------------------------------------------------------------
// Winner selection (exact reference math), 1 block x 1024 threads.
// Threads 0-511 own a feature; the O(K^2) rank scan is split across 2
// threads per feature (1024 total), combined via shared counts.
// ---------------------------------------------------------------------------
__global__ void __launch_bounds__(1024, 1)
winner_kernel(float* __restrict__ out) {
    __shared__ float tot_s[KFEAT];
    __shared__ int   cnt_s[1024];
    __shared__ float red_s[16];
    __shared__ float v_s;

    const int tid  = threadIdx.x;
    const int k    = tid & (KFEAT - 1);
    const int half = tid >> 9;

    float pot[TT];
    int nspk = 0;
    float value = 0.0f;

    if (half == 0) {
#pragma unroll
        for (int t = 0; t < TT; t++) {
            float dd = g_dot[t * KFEAT + k];
            float p = (dd > THRESH) ? dd : 0.0f;
            pot[t] = p;
            nspk += (p > 0.0f) ? 1 : 0;
        }
        int first = TT - nspk;
        if (first > TT - 1) first = TT - 1;
        if (first < 0) first = 0;
        float dv = g_dot[first * KFEAT + k];
        value = (dv > THRESH) ? dv : 0.0f;
        float sval = (nspk > 0) ? value : 0.0f;

        float m = sval;
#pragma unroll
        for (int o = 16; o > 0; o >>= 1)
            m = fmaxf(m, __shfl_xor_sync(0xffffffffu, m, o));
        if ((k & 31) == 0) red_s[k >> 5] = m;
    }
    __syncthreads();
    if (tid == 0) {
        float mm = red_s[0];
#pragma unroll
        for (int i = 1; i < 16; i++) mm = fmaxf(mm, red_s[i]);
        v_s = mm * (float)TT;
    }
    __syncthreads();

    if (half == 0) {
        const float fns = (float)nspk;
        tot_s[k] = fns * value + fns * v_s;
    }
    __syncthreads();

    // rank-count: each thread scans 256 entries (64 float4)
    const float total = tot_s[k];
    int cnt = 0;
    const float4* t4 = (const float4*)tot_s + half * 64;
    const int jbase = half * 256;
#pragma unroll 8
    for (int jj = 0; jj < 64; jj++) {
        float4 tv = t4[jj];
        const int j0 = jbase + jj * 4;
        cnt += ((tv.x > total) || (tv.x == total && (j0 + 0) < k)) ? 1 : 0;
        cnt += ((tv.y > total) || (tv.y == total && (j0 + 1) < k)) ? 1 : 0;
        cnt += ((tv.z > total) || (tv.z == total && (j0 + 2) < k)) ? 1 : 0;
        cnt += ((tv.w > total) || (tv.w == total && (j0 + 3) < k)) ? 1 : 0;
    }
    cnt_s[tid] = cnt;
    __syncthreads();

    if (half == 0) {
        const int c = cnt_s[k] + cnt_s[k + 512];
        const bool win = (total > 0.0f) && (c < KWTA);
#pragma unroll
        for (int t = 0; t < TT; t++)
            out[t * KFEAT + k] = (win && pot[t] > 0.0f) ? 1.0f : 0.0f;
    }
}

// ---------------------------------------------------------------------------
extern "C" void kernel_launch(void* const* d_in, const int* in_sizes, int n_in,
                              void* d_out, int out_size) {
    const float* a = (const float*)d_in[0];
    const float* b = (const float*)d_in[1];
    const float* rec = a;
    const float* wgt = b;
    if (in_sizes[0] > in_sizes[1]) { rec = b; wgt = a; }

    cudaFuncSetAttribute(gemm_kernel,
                         cudaFuncAttributeMaxDynamicSharedMemorySize, SMEMB);

    conv_kernel<<<(KPAD / 4 + 255) / 256, 256>>>(rec);
    dim3 grid(SPLITS, 4);
    gemm_kernel<<<grid, 256, SMEMB>>>(wgt);
    reduce_kernel<<<(TT * KFEAT) / 256, 256>>>();
    winner_kernel<<<1, 1024>>>((float*)d_out);
}

// round 6
// speedup vs baseline: 2.3816x; 1.1939x over previous
#include <cuda_runtime.h>
#include <cuda_bf16.h>
#include <cstdint>

// ---------------------------------------------------------------------------
// Problem constants
#define NRED   100000
#define TT     32
#define KFEAT  512
#define THRESH 10.0f
#define KWTA   16

// GEMM tiling: 37 k-splits x 8 m-tiles = 296 CTAs (2 co-resident waves)
#define SPLITS 37
#define KTILE  64
#define NT     43
#define CHUNK  (KTILE * NT)        // 2752
#define MTILE  64

// smem: A: 2 bufs x [128 rows][128B] bf16 (hi rows 0-63, lo rows 64-127)
//       B: 2 bufs x [64 rows][128B] bf16 (hi t 0-31, lo t 32-63)
#define SM_A    0
#define SM_ASTG 16384
#define SM_B    (2 * SM_ASTG)      // 32768
#define SM_BSTG 8192
#define SMEMB   (SM_B + 2 * SM_BSTG)   // 49152

// Device scratch (static — no dynamic allocation allowed)
__device__ float g_partial[SPLITS * TT * KFEAT];   // [split][t][feat]
__device__ float g_dot[TT * KFEAT];                // [t][feat]

// ---------------------------------------------------------------------------
__device__ __forceinline__ uint32_t smem_u32(const void* p) {
    uint32_t a;
    asm("{ .reg .u64 t; cvta.to.shared.u64 t, %1; cvt.u32.u64 %0, t; }"
        : "=r"(a) : "l"(p));
    return a;
}
__device__ __forceinline__ uint32_t sw128(uint32_t off) {
    return off ^ ((off >> 3) & 0x70);
}
__device__ __forceinline__ uint32_t packbf(__nv_bfloat16 a, __nv_bfloat16 b) {
    __nv_bfloat162 v; v.x = a; v.y = b;
    return *reinterpret_cast<uint32_t*>(&v);
}
__device__ __forceinline__ void split2(float x, __nv_bfloat16& h, __nv_bfloat16& l) {
    h = __float2bfloat16(x);
    l = __float2bfloat16(x - __bfloat162float(h));
}
#define LDSM4(R, ADDR)                                                        \
    asm volatile("ldmatrix.sync.aligned.m8n8.x4.shared.b16 {%0,%1,%2,%3}, [%4];" \
                 : "=r"((R)[0]), "=r"((R)[1]), "=r"((R)[2]), "=r"((R)[3])     \
                 : "r"(ADDR))
#define MMA16816(D, A, B0, B1)                                                \
    asm volatile("mma.sync.aligned.m16n8k16.row.col.f32.bf16.bf16.f32 "       \
                 "{%0,%1,%2,%3}, {%4,%5,%6,%7}, {%8,%9}, {%0,%1,%2,%3};"      \
                 : "+f"((D)[0]), "+f"((D)[1]), "+f"((D)[2]), "+f"((D)[3])     \
                 : "r"((A)[0]), "r"((A)[1]), "r"((A)[2]), "r"((A)[3]),        \
                   "r"(B0), "r"(B1))

// ---------------------------------------------------------------------------
// GEMM: bf16 3-term split (hi*hi + hi*lo + lo*hi), fused R-split in B loader.
// grid (37, 8), 256 threads, 2 CTAs/SM.
// Warps 0-3: A(hi+lo) x B-hi (n-cols 0-31 = t). Warps 4-7: A-hi x B-lo
// (stacked cols 32-63 = same t, lo plane). Epilogue folds via smem.
// ---------------------------------------------------------------------------
__global__ void __launch_bounds__(256, 2)
gemm_kernel(const float* __restrict__ W, const float* __restrict__ R) {
    extern __shared__ char smem[];
    const uint32_t sb = smem_u32(smem);

    const int tid  = threadIdx.x;
    const int lane = tid & 31;
    const int wrp  = tid >> 5;
    const int split = blockIdx.x;
    const int m0    = blockIdx.y * MTILE;
    const int kbase = split * CHUNK;

    // W loader: warp = 2 rows x 16 k-quads; 4 row-iters -> 64 rows
    const int row_off = lane >> 4;            // 0..1
    const int kq      = lane & 15;            // 0..15
    // B loader (fused split): thread = 1 t-row x 8 floats
    const int trow = tid >> 3;                // 0..31
    const int kq8  = tid & 7;                 // 0..7

    // ldmatrix indices
    const int mwarp = (wrp & 3) * 16;
    const int nhalf = wrp >> 2;               // 0: B-hi, 1: B-lo
    const int arow = mwarp + (lane & 7) + ((lane >> 3) & 1) * 8;
    const uint32_t a_rb  = (uint32_t)arow * 128;
    const uint32_t a_xr  = (uint32_t)(arow & 7) << 4;
    const uint32_t a_kb0 = ((lane >> 4) & 1) * 16;
    const int browl = (lane & 7) + ((lane >> 4) & 1) * 8;
    const uint32_t b_rb  = (uint32_t)browl * 128 + (uint32_t)nhalf * 4096;
    const uint32_t b_xr  = (uint32_t)(lane & 7) << 4;
    const uint32_t b_kb0 = ((lane >> 3) & 1) * 16;

    float d[4][4];
#pragma unroll
    for (int i = 0; i < 4; i++)
#pragma unroll
        for (int j = 0; j < 4; j++) d[i][j] = 0.0f;

    float4 wr[4];
    float4 br0, br1;
    const float4 z4 = make_float4(0.f, 0.f, 0.f, 0.f);

#define LOAD_TILE(TL) do {                                                   \
    const int kp_ = kbase + (TL) * KTILE + kq * 4;                           \
    const bool ok_ = (kp_ < NRED);                                           \
    const float* wp_ = W + (size_t)(m0 + wrp * 2 + row_off) * NRED + kp_;    \
    _Pragma("unroll")                                                        \
    for (int i = 0; i < 4; i++)                                              \
        wr[i] = ok_ ? *(const float4*)(wp_ + (size_t)16 * i * NRED) : z4;    \
    const int kp8_ = kbase + (TL) * KTILE + kq8 * 8;                         \
    const bool okb_ = (kp8_ < NRED);                                         \
    const float* rp_ = R + (size_t)trow * NRED + kp8_;                       \
    br0 = okb_ ? *(const float4*)(rp_)     : z4;                             \
    br1 = okb_ ? *(const float4*)(rp_ + 4) : z4;                             \
} while (0)

#define STS_TILE(BUF) do {                                                   \
    char* ab_ = smem + SM_A + (BUF) * SM_ASTG;                               \
    _Pragma("unroll")                                                        \
    for (int i = 0; i < 4; i++) {                                            \
        const int row_ = i * 16 + wrp * 2 + row_off;                         \
        const uint32_t sw_ = sw128((uint32_t)row_ * 128 + kq * 8);           \
        float4 f_ = wr[i];                                                   \
        __nv_bfloat16 h0,h1,h2,h3,l0,l1,l2,l3;                               \
        split2(f_.x, h0, l0); split2(f_.y, h1, l1);                          \
        split2(f_.z, h2, l2); split2(f_.w, h3, l3);                          \
        *(uint2*)(ab_ + sw_)        = make_uint2(packbf(h0,h1), packbf(h2,h3)); \
        *(uint2*)(ab_ + sw_ + 8192) = make_uint2(packbf(l0,l1), packbf(l2,l3)); \
    }                                                                        \
    char* bb_ = smem + SM_B + (BUF) * SM_BSTG;                               \
    {                                                                        \
        __nv_bfloat16 h0,h1,h2,h3,h4,h5,h6,h7,l0,l1,l2,l3,l4,l5,l6,l7;       \
        split2(br0.x,h0,l0); split2(br0.y,h1,l1);                            \
        split2(br0.z,h2,l2); split2(br0.w,h3,l3);                            \
        split2(br1.x,h4,l4); split2(br1.y,h5,l5);                            \
        split2(br1.z,h6,l6); split2(br1.w,h7,l7);                            \
        const uint32_t bo_ = (uint32_t)trow * 128 + kq8 * 16;                \
        *(uint4*)(bb_ + sw128(bo_)) =                                        \
            make_uint4(packbf(h0,h1), packbf(h2,h3), packbf(h4,h5), packbf(h6,h7)); \
        *(uint4*)(bb_ + sw128(bo_ + 4096)) =                                 \
            make_uint4(packbf(l0,l1), packbf(l2,l3), packbf(l4,l5), packbf(l6,l7)); \
    }                                                                        \
} while (0)

// warps 0-3: A-hi x B-hi + A-lo x B-hi; warps 4-7: A-hi x B-lo only
#define COMPUTE(BUF) do {                                                    \
    const uint32_t sa_ = sb + SM_A + (BUF) * SM_ASTG;                        \
    const uint32_t sB_ = sb + SM_B + (BUF) * SM_BSTG;                        \
    _Pragma("unroll")                                                        \
    for (int ks = 0; ks < 4; ks++) {                                         \
        uint32_t ah[4], al[4], bf[2][4];                                     \
        const uint32_t akb_ = ((uint32_t)(ks * 32) + a_kb0) ^ a_xr;          \
        LDSM4(ah, sa_ + a_rb + akb_);                                        \
        const uint32_t bkb_ = ((uint32_t)(ks * 32) + b_kb0) ^ b_xr;          \
        LDSM4(bf[0], sB_ + b_rb + bkb_);                                     \
        LDSM4(bf[1], sB_ + 2048 + b_rb + bkb_);                              \
        MMA16816(d[0], ah, bf[0][0], bf[0][1]);                              \
        MMA16816(d[1], ah, bf[0][2], bf[0][3]);                              \
        MMA16816(d[2], ah, bf[1][0], bf[1][1]);                              \
        MMA16816(d[3], ah, bf[1][2], bf[1][3]);                              \
        if (nhalf == 0) {                                                    \
            LDSM4(al, sa_ + 8192 + a_rb + akb_);                             \
            MMA16816(d[0], al, bf[0][0], bf[0][1]);                          \
            MMA16816(d[1], al, bf[0][2], bf[0][3]);                          \
            MMA16816(d[2], al, bf[1][0], bf[1][1]);                          \
            MMA16816(d[3], al, bf[1][2], bf[1][3]);                          \
        }                                                                    \
    }                                                                        \
} while (0)

    LOAD_TILE(0);
    STS_TILE(0);
    __syncthreads();

    for (int tl = 0; tl < NT; tl++) {
        if (tl + 1 < NT) LOAD_TILE(tl + 1);
        COMPUTE(tl & 1);
        if (tl + 1 < NT) {
            STS_TILE((tl + 1) & 1);
            __syncthreads();
        }
    }

    // ---- epilogue: fold B-lo contribution (warps 4-7) into warps 0-3 ----
    __syncthreads();                       // smem tiles now dead, reuse
    float* es = (float*)smem;
    const int eidx = ((wrp & 3) * 32 + lane) * 17;
    if (nhalf == 1) {
#pragma unroll
        for (int i = 0; i < 4; i++)
#pragma unroll
            for (int j = 0; j < 4; j++) es[eidx + i * 4 + j] = d[i][j];
    }
    __syncthreads();
    if (nhalf == 0) {
        const int rr = mwarp + (lane >> 2);
        const int c0 = (lane & 3) * 2;
        float* gp = g_partial + (size_t)split * (TT * KFEAT) + m0;
#pragma unroll
        for (int nt = 0; nt < 4; nt++) {
            const int t0 = nt * 8 + c0;
            float v0 = d[nt][0] + es[eidx + nt * 4 + 0];
            float v1 = d[nt][1] + es[eidx + nt * 4 + 1];
            float v2 = d[nt][2] + es[eidx + nt * 4 + 2];
            float v3 = d[nt][3] + es[eidx + nt * 4 + 3];
            gp[(size_t)t0 * KFEAT + rr]           = v0;
            gp[(size_t)(t0 + 1) * KFEAT + rr]     = v1;
            gp[(size_t)t0 * KFEAT + rr + 8]       = v2;
            gp[(size_t)(t0 + 1) * KFEAT + rr + 8] = v3;
        }
    }
}

// ---------------------------------------------------------------------------
// Reduce partials across splits: g_dot[t][feat]
// ---------------------------------------------------------------------------
__global__ void __launch_bounds__(256)
reduce_kernel() {
    const int j = blockIdx.x * 256 + threadIdx.x;
    float s = 0.0f;
#pragma unroll 8
    for (int sp = 0; sp < SPLITS; sp++) s += g_partial[sp * (TT * KFEAT) + j];
    g_dot[j] = s;
}

// ---------------------------------------------------------------------------
// Winner selection: 512 threads compute totals; warp 0 runs the 16-round
// suppressive argmax (exact reference semantics incl. index tie-break).
// ---------------------------------------------------------------------------
__global__ void __launch_bounds__(512, 1)
winner_kernel(float* __restrict__ out) {
    __shared__ float tot_s[KFEAT];
    __shared__ int   win_s[KFEAT];
    __shared__ float red_s[16];
    __shared__ float v_s;

    const int k = threadIdx.x;

    float pot[TT];
    int nspk = 0;
#pragma unroll
    for (int t = 0; t < TT; t++) {
        float dd = g_dot[t * KFEAT + k];
        float p = (dd > THRESH) ? dd : 0.0f;
        pot[t] = p;
        nspk += (p > 0.0f) ? 1 : 0;
    }
    int first = TT - nspk;
    if (first > TT - 1) first = TT - 1;
    if (first < 0) first = 0;
    float dv = g_dot[first * KFEAT + k];
    float value = (dv > THRESH) ? dv : 0.0f;
    float sval = (nspk > 0) ? value : 0.0f;

    float m = sval;
#pragma unroll
    for (int o = 16; o > 0; o >>= 1)
        m = fmaxf(m, __shfl_xor_sync(0xffffffffu, m, o));
    if ((k & 31) == 0) red_s[k >> 5] = m;
    win_s[k] = 0;
    __syncthreads();
    if (k == 0) {
        float mm = red_s[0];
#pragma unroll
        for (int i = 1; i < 16; i++) mm = fmaxf(mm, red_s[i]);
        v_s = mm * (float)TT;
    }
    __syncthreads();

    const float fns = (float)nspk;
    tot_s[k] = fns * value + fns * v_s;
    __syncthreads();

    // warp 0: 16 rounds of argmax (min-index tie-break), zeroing winners
    if (k < 32) {
        float tv[16];
#pragma unroll
        for (int i = 0; i < 16; i++) tv[i] = tot_s[i * 32 + k];

        for (int r = 0; r < KWTA; r++) {
            float bv = tv[0];
            int   bi = k;
#pragma unroll
            for (int i = 1; i < 16; i++) {
                if (tv[i] > bv) { bv = tv[i]; bi = i * 32 + k; }
            }
#pragma unroll
            for (int o = 16; o > 0; o >>= 1) {
                float ov = __shfl_xor_sync(0xffffffffu, bv, o);
                int   oi = __shfl_xor_sync(0xffffffffu, bi, o);
                if (ov > bv || (ov == bv && oi < bi)) { bv = ov; bi = oi; }
            }
            if (bv == 0.0f) break;           // uniform after reduction
            if (k == (bi & 31)) {
                const int slot = bi >> 5;
#pragma unroll
                for (int i = 0; i < 16; i++)
                    if (i == slot) tv[i] = 0.0f;
            }
            if (k == 0) win_s[bi] = 1;
        }
    }
    __syncthreads();

    const bool win = (win_s[k] != 0);
#pragma unroll
    for (int t = 0; t < TT; t++)
        out[t * KFEAT + k] = (win && pot[t] > 0.0f) ? 1.0f : 0.0f;
}

// ---------------------------------------------------------------------------
extern "C" void kernel_launch(void* const* d_in, const int* in_sizes, int n_in,
                              void* d_out, int out_size) {
    const float* a = (const float*)d_in[0];
    const float* b = (const float*)d_in[1];
    const float* rec = a;
    const float* wgt = b;
    if (in_sizes[0] > in_sizes[1]) { rec = b; wgt = a; }

    cudaFuncSetAttribute(gemm_kernel,
                         cudaFuncAttributeMaxDynamicSharedMemorySize, SMEMB);

    dim3 grid(SPLITS, 8);
    gemm_kernel<<<grid, 256, SMEMB>>>(wgt, rec);
    reduce_kernel<<<(TT * KFEAT) / 256, 256>>>();
    winner_kernel<<<1, 512>>>((float*)d_out);
}

// round 7
// speedup vs baseline: 2.4757x; 1.0395x over previous
#include <cuda_runtime.h>
#include <cuda_bf16.h>
#include <cstdint>

// ---------------------------------------------------------------------------
// Problem constants
#define NRED   100000
#define TT     32
#define KFEAT  512
#define THRESH 10.0f
#define KWTA   16

// GEMM tiling: 74 k-splits x 4 m-tiles = 296 CTAs (2 CTAs/SM)
#define SPLITS 74
#define KTILE  64
#define NT     22
#define CHUNK  (KTILE * NT)        // 1408
#define KPAD   (SPLITS * CHUNK)    // 104192
#define MTILE  128

// smem: A: 2 bufs x 32KB (hi plane 16KB rows 0-127, lo plane +16KB)
//       B: 2 bufs x 8KB  (hi t 0-31 rows, lo t rows 32-63)
#define SM_A    0
#define SM_ASTG 32768
#define SM_B    (2 * SM_ASTG)      // 65536
#define SM_BSTG 8192
#define SMEMB   (SM_B + 2 * SM_BSTG)   // 81920

// Device scratch (static — no dynamic allocation allowed)
__device__ __align__(128) __nv_bfloat16 g_B[(size_t)64 * KPAD];  // 13.3MB
__device__ float g_partial[SPLITS * TT * KFEAT];   // [split][t][feat] 4.85MB... x74
__device__ float g_dot[TT * KFEAT];                // [t][feat]

// ---------------------------------------------------------------------------
__device__ __forceinline__ uint32_t smem_u32(const void* p) {
    uint32_t a;
    asm("{ .reg .u64 t; cvta.to.shared.u64 t, %1; cvt.u32.u64 %0, t; }"
        : "=r"(a) : "l"(p));
    return a;
}
__device__ __forceinline__ uint32_t sw128(uint32_t off) {
    return off ^ ((off >> 3) & 0x70);
}
__device__ __forceinline__ uint32_t packbf(__nv_bfloat16 a, __nv_bfloat16 b) {
    __nv_bfloat162 v; v.x = a; v.y = b;
    return *reinterpret_cast<uint32_t*>(&v);
}
__device__ __forceinline__ void split2(float x, __nv_bfloat16& h, __nv_bfloat16& l) {
    h = __float2bfloat16(x);
    l = __float2bfloat16(x - __bfloat162float(h));
}
__device__ __forceinline__ void cpasync16(uint32_t dst, const void* src) {
    asm volatile("cp.async.cg.shared.global [%0], [%1], 16;"
                 :: "r"(dst), "l"(src) : "memory");
}
__device__ __forceinline__ void cpasync_commit() {
    asm volatile("cp.async.commit_group;" ::: "memory");
}
__device__ __forceinline__ void cpasync_wait0() {
    asm volatile("cp.async.wait_group 0;" ::: "memory");
}
#define LDSM4(R, ADDR)                                                        \
    asm volatile("ldmatrix.sync.aligned.m8n8.x4.shared.b16 {%0,%1,%2,%3}, [%4];" \
                 : "=r"((R)[0]), "=r"((R)[1]), "=r"((R)[2]), "=r"((R)[3])     \
                 : "r"(ADDR))
#define MMA16816(D, A, B0, B1)                                                \
    asm volatile("mma.sync.aligned.m16n8k16.row.col.f32.bf16.bf16.f32 "       \
                 "{%0,%1,%2,%3}, {%4,%5,%6,%7}, {%8,%9}, {%0,%1,%2,%3};"      \
                 : "+f"((D)[0]), "+f"((D)[1]), "+f"((D)[2]), "+f"((D)[3])     \
                 : "r"((A)[0]), "r"((A)[1]), "r"((A)[2]), "r"((A)[3]),        \
                   "r"(B0), "r"(B1))

// ---------------------------------------------------------------------------
// Split rec_field into bf16 hi/lo (vectorized): g_B[t]=hi, g_B[t+32]=lo,
// zero-padded out to KPAD.
// ---------------------------------------------------------------------------
__global__ void __launch_bounds__(256)
conv_kernel(const float* __restrict__ R) {
    const int k4 = (blockIdx.x * 256 + threadIdx.x) * 4;
    if (k4 >= KPAD) return;
    const bool ok = (k4 < NRED);
#pragma unroll 4
    for (int t = 0; t < TT; t++) {
        float4 x = ok ? *(const float4*)(R + (size_t)t * NRED + k4)
                      : make_float4(0.f, 0.f, 0.f, 0.f);
        __nv_bfloat16 h0,h1,h2,h3,l0,l1,l2,l3;
        split2(x.x, h0, l0); split2(x.y, h1, l1);
        split2(x.z, h2, l2); split2(x.w, h3, l3);
        *(uint2*)(g_B + (size_t)t * KPAD + k4)        = make_uint2(packbf(h0,h1), packbf(h2,h3));
        *(uint2*)(g_B + (size_t)(t + 32) * KPAD + k4) = make_uint2(packbf(l0,l1), packbf(l2,l3));
    }
}

// ---------------------------------------------------------------------------
// GEMM: bf16 3-term split. grid (74, 4), 256 threads, 2 CTAs/SM.
// Warp pairs (q, q+4), q=wrp&3, own strips {2q, 2q+1} (16 rows each):
//   grp0 (wrp<4):  d0 += (ah0+al0) x bh ; d1 += (ah1+al1) x bh   (16 MMA/ks)
//   grp1 (wrp>=4): e0 += ah0 x bl ;       e1 += ah1 x bl          (8 MMA/ks)
// Epilogue folds e into d via smem.
// ---------------------------------------------------------------------------
__global__ void __launch_bounds__(256, 2)
gemm_kernel(const float* __restrict__ W) {
    extern __shared__ char smem[];
    const uint32_t sb = smem_u32(smem);

    const int tid  = threadIdx.x;
    const int lane = tid & 31;
    const int wrp  = tid >> 5;
    const int q    = wrp & 3;
    const int grp  = wrp >> 2;
    const int split = blockIdx.x;
    const int m0    = blockIdx.y * MTILE;
    const int kbase = split * CHUNK;

    // W loader: warp = 2 rows x 16 kq, 8 iters -> 128 rows
    const int row_off = lane >> 4;
    const int kq      = lane & 15;
    // B cp.async loader: thread = row (tid>>2), 2x16B units
    const int brow = tid >> 2;                 // 0..63
    const uint32_t bcol = (uint32_t)(tid & 3) * 32;  // byte col 0..96

    // ldmatrix A: two strips
    const int s0 = 2 * q, s1 = 2 * q + 1;
    const int arow0 = s0 * 16 + (lane & 7) + ((lane >> 3) & 1) * 8;
    const int arow1 = s1 * 16 + (lane & 7) + ((lane >> 3) & 1) * 8;
    const uint32_t a_kb0 = ((lane >> 4) & 1) * 16;
    const uint32_t a_off0 = (uint32_t)arow0 * 128;
    const uint32_t a_off1 = (uint32_t)arow1 * 128;
    const uint32_t a_xr0  = (uint32_t)(arow0 & 7) << 4;
    const uint32_t a_xr1  = (uint32_t)(arow1 & 7) << 4;
    // ldmatrix B: plane by group
    const int browl = (lane & 7) + ((lane >> 4) & 1) * 8;
    const uint32_t b_rb  = (uint32_t)browl * 128 + (uint32_t)grp * 4096;
    const uint32_t b_xr  = (uint32_t)(lane & 7) << 4;
    const uint32_t b_kb0 = ((lane >> 3) & 1) * 16;

    float d[2][4][4];
#pragma unroll
    for (int s = 0; s < 2; s++)
#pragma unroll
        for (int i = 0; i < 4; i++)
#pragma unroll
            for (int j = 0; j < 4; j++) d[s][i][j] = 0.0f;

    float4 wr[8];
    const float4 z4 = make_float4(0.f, 0.f, 0.f, 0.f);

#define LOAD_W(TL) do {                                                      \
    const int kp_ = kbase + (TL) * KTILE + kq * 4;                           \
    const bool ok_ = (kp_ < NRED);                                           \
    const float* wp_ = W + (size_t)(m0 + wrp * 2 + row_off) * NRED + kp_;    \
    _Pragma("unroll")                                                        \
    for (int i = 0; i < 8; i++)                                              \
        wr[i] = ok_ ? *(const float4*)(wp_ + (size_t)16 * i * NRED) : z4;    \
} while (0)

#define ASYNC_B(TL, BUF) do {                                                \
    const __nv_bfloat16* src_ = g_B + (size_t)brow * KPAD                    \
                              + (kbase + (TL) * KTILE) + (bcol >> 1);        \
    const uint32_t db_ = sb + SM_B + (BUF) * SM_BSTG;                        \
    const uint32_t bo_ = (uint32_t)brow * 128 + bcol;                        \
    cpasync16(db_ + sw128(bo_),      src_);                                  \
    cpasync16(db_ + sw128(bo_ + 16), src_ + 8);                              \
    cpasync_commit();                                                        \
} while (0)

#define STS_A(BUF) do {                                                      \
    char* ab_ = smem + SM_A + (BUF) * SM_ASTG;                               \
    _Pragma("unroll")                                                        \
    for (int i = 0; i < 8; i++) {                                            \
        const int row_ = i * 16 + wrp * 2 + row_off;                         \
        const uint32_t sw_ = sw128((uint32_t)row_ * 128 + kq * 8);           \
        float4 f_ = wr[i];                                                   \
        __nv_bfloat16 h0,h1,h2,h3,l0,l1,l2,l3;                               \
        split2(f_.x, h0, l0); split2(f_.y, h1, l1);                          \
        split2(f_.z, h2, l2); split2(f_.w, h3, l3);                          \
        *(uint2*)(ab_ + sw_)         = make_uint2(packbf(h0,h1), packbf(h2,h3)); \
        *(uint2*)(ab_ + sw_ + 16384) = make_uint2(packbf(l0,l1), packbf(l2,l3)); \
    }                                                                        \
} while (0)

#define COMPUTE(BUF) do {                                                    \
    const uint32_t sa_ = sb + SM_A + (BUF) * SM_ASTG;                        \
    const uint32_t sB_ = sb + SM_B + (BUF) * SM_BSTG;                        \
    _Pragma("unroll")                                                        \
    for (int ks = 0; ks < 4; ks++) {                                         \
        uint32_t ah0[4], ah1[4], bf[2][4];                                   \
        const uint32_t kb_ = (uint32_t)(ks * 32) + a_kb0;                    \
        LDSM4(ah0, sa_ + a_off0 + (kb_ ^ a_xr0));                            \
        LDSM4(ah1, sa_ + a_off1 + (kb_ ^ a_xr1));                            \
        const uint32_t bkb_ = ((uint32_t)(ks * 32) + b_kb0) ^ b_xr;          \
        LDSM4(bf[0], sB_ + b_rb + bkb_);                                     \
        LDSM4(bf[1], sB_ + 2048 + b_rb + bkb_);                              \
        MMA16816(d[0][0], ah0, bf[0][0], bf[0][1]);                          \
        MMA16816(d[0][1], ah0, bf[0][2], bf[0][3]);                          \
        MMA16816(d[0][2], ah0, bf[1][0], bf[1][1]);                          \
        MMA16816(d[0][3], ah0, bf[1][2], bf[1][3]);                          \
        MMA16816(d[1][0], ah1, bf[0][0], bf[0][1]);                          \
        MMA16816(d[1][1], ah1, bf[0][2], bf[0][3]);                          \
        MMA16816(d[1][2], ah1, bf[1][0], bf[1][1]);                          \
        MMA16816(d[1][3], ah1, bf[1][2], bf[1][3]);                          \
        if (grp == 0) {                                                      \
            uint32_t al0[4], al1[4];                                         \
            LDSM4(al0, sa_ + 16384 + a_off0 + (kb_ ^ a_xr0));                \
            LDSM4(al1, sa_ + 16384 + a_off1 + (kb_ ^ a_xr1));                \
            MMA16816(d[0][0], al0, bf[0][0], bf[0][1]);                      \
            MMA16816(d[0][1], al0, bf[0][2], bf[0][3]);                      \
            MMA16816(d[0][2], al0, bf[1][0], bf[1][1]);                      \
            MMA16816(d[0][3], al0, bf[1][2], bf[1][3]);                      \
            MMA16816(d[1][0], al1, bf[0][0], bf[0][1]);                      \
            MMA16816(d[1][1], al1, bf[0][2], bf[0][3]);                      \
            MMA16816(d[1][2], al1, bf[1][0], bf[1][1]);                      \
            MMA16816(d[1][3], al1, bf[1][2], bf[1][3]);                      \
        }                                                                    \
    }                                                                        \
} while (0)

    // prologue
    ASYNC_B(0, 0);
    LOAD_W(0);
    STS_A(0);
    cpasync_wait0();
    __syncthreads();

    for (int tl = 0; tl < NT; tl++) {
        if (tl + 1 < NT) {
            ASYNC_B(tl + 1, (tl + 1) & 1);
            LOAD_W(tl + 1);
        }
        COMPUTE(tl & 1);
        if (tl + 1 < NT) {
            STS_A((tl + 1) & 1);
            cpasync_wait0();
            __syncthreads();
        }
    }

    // ---- epilogue: fold grp1 (e) into grp0 (d), write g_partial ----
    __syncthreads();
    float* es = (float*)smem;
    const int eidx = (q * 32 + lane) * 33;
    if (grp == 1) {
#pragma unroll
        for (int s = 0; s < 2; s++)
#pragma unroll
            for (int i = 0; i < 4; i++)
#pragma unroll
                for (int j = 0; j < 4; j++)
                    es[eidx + s * 16 + i * 4 + j] = d[s][i][j];
    }
    __syncthreads();
    if (grp == 0) {
        float* gp = g_partial + (size_t)split * (TT * KFEAT) + m0;
        const int rbase = lane >> 2;
        const int c0 = (lane & 3) * 2;
#pragma unroll
        for (int s = 0; s < 2; s++) {
            const int feat = (2 * q + s) * 16 + rbase;
#pragma unroll
            for (int nt = 0; nt < 4; nt++) {
                const int t0 = nt * 8 + c0;
                float v0 = d[s][nt][0] + es[eidx + s * 16 + nt * 4 + 0];
                float v1 = d[s][nt][1] + es[eidx + s * 16 + nt * 4 + 1];
                float v2 = d[s][nt][2] + es[eidx + s * 16 + nt * 4 + 2];
                float v3 = d[s][nt][3] + es[eidx + s * 16 + nt * 4 + 3];
                gp[(size_t)t0 * KFEAT + feat]           = v0;
                gp[(size_t)(t0 + 1) * KFEAT + feat]     = v1;
                gp[(size_t)t0 * KFEAT + feat + 8]       = v2;
                gp[(size_t)(t0 + 1) * KFEAT + feat + 8] = v3;
            }
        }
    }
}

// ---------------------------------------------------------------------------
// Reduce partials across splits: g_dot[t][feat]
// ---------------------------------------------------------------------------
__global__ void __launch_bounds__(256)
reduce_kernel() {
    const int j = blockIdx.x * 256 + threadIdx.x;
    float s = 0.0f;
#pragma unroll 8
    for (int sp = 0; sp < SPLITS; sp++) s += g_partial[sp * (TT * KFEAT) + j];
    g_dot[j] = s;
}

// ---------------------------------------------------------------------------
// Winner selection: 512 threads compute totals; warp 0 runs the 16-round
// suppressive argmax (exact reference semantics incl. index tie-break).
// ---------------------------------------------------------------------------
__global__ void __launch_bounds__(512, 1)
winner_kernel(float* __restrict__ out) {
    __shared__ float tot_s[KFEAT];
    __shared__ int   win_s[KFEAT];
    __shared__ float red_s[16];
    __shared__ float v_s;

    const int k = threadIdx.x;

    float pot[TT];
    int nspk = 0;
#pragma unroll
    for (int t = 0; t < TT; t++) {
        float dd = g_dot[t * KFEAT + k];
        float p = (dd > THRESH) ? dd : 0.0f;
        pot[t] = p;
        nspk += (p > 0.0f) ? 1 : 0;
    }
    int first = TT - nspk;
    if (first > TT - 1) first = TT - 1;
    if (first < 0) first = 0;
    float dv = g_dot[first * KFEAT + k];
    float value = (dv > THRESH) ? dv : 0.0f;
    float sval = (nspk > 0) ? value : 0.0f;

    float m = sval;
#pragma unroll
    for (int o = 16; o > 0; o >>= 1)
        m = fmaxf(m, __shfl_xor_sync(0xffffffffu, m, o));
    if ((k & 31) == 0) red_s[k >> 5] = m;
    win_s[k] = 0;
    __syncthreads();
    if (k == 0) {
        float mm = red_s[0];
#pragma unroll
        for (int i = 1; i < 16; i++) mm = fmaxf(mm, red_s[i]);
        v_s = mm * (float)TT;
    }
    __syncthreads();

    const float fns = (float)nspk;
    tot_s[k] = fns * value + fns * v_s;
    __syncthreads();

    if (k < 32) {
        float tv[16];
#pragma unroll
        for (int i = 0; i < 16; i++) tv[i] = tot_s[i * 32 + k];

        for (int r = 0; r < KWTA; r++) {
            float bv = tv[0];
            int   bi = k;
#pragma unroll
            for (int i = 1; i < 16; i++) {
                if (tv[i] > bv) { bv = tv[i]; bi = i * 32 + k; }
            }
#pragma unroll
            for (int o = 16; o > 0; o >>= 1) {
                float ov = __shfl_xor_sync(0xffffffffu, bv, o);
                int   oi = __shfl_xor_sync(0xffffffffu, bi, o);
                if (ov > bv || (ov == bv && oi < bi)) { bv = ov; bi = oi; }
            }
            if (bv == 0.0f) break;
            if (k == (bi & 31)) {
                const int slot = bi >> 5;
#pragma unroll
                for (int i = 0; i < 16; i++)
                    if (i == slot) tv[i] = 0.0f;
            }
            if (k == 0) win_s[bi] = 1;
        }
    }
    __syncthreads();

    const bool win = (win_s[k] != 0);
#pragma unroll
    for (int t = 0; t < TT; t++)
        out[t * KFEAT + k] = (win && pot[t] > 0.0f) ? 1.0f : 0.0f;
}

// ---------------------------------------------------------------------------
extern "C" void kernel_launch(void* const* d_in, const int* in_sizes, int n_in,
                              void* d_out, int out_size) {
    const float* a = (const float*)d_in[0];
    const float* b = (const float*)d_in[1];
    const float* rec = a;
    const float* wgt = b;
    if (in_sizes[0] > in_sizes[1]) { rec = b; wgt = a; }

    cudaFuncSetAttribute(gemm_kernel,
                         cudaFuncAttributeMaxDynamicSharedMemorySize, SMEMB);

    conv_kernel<<<(KPAD / 4 + 255) / 256, 256>>>(rec);
    dim3 grid(SPLITS, 4);
    gemm_kernel<<<grid, 256, SMEMB>>>(wgt);
    reduce_kernel<<<(TT * KFEAT) / 256, 256>>>();
    winner_kernel<<<1, 512>>>((float*)d_out);
}